// round 7
// baseline (speedup 1.0000x reference)
#include <cuda_runtime.h>

// Shapes (fixed by the problem)
#define BB   4
#define CC   128
#define NPTS 8192
#define KNN  16
#define OO   128
// derived
#define PTS_TOTAL (BB*NPTS)          // 32768
#define CNT1 32768.0f                // B*N      (stats count for central channels)
#define CNT2 524288.0f               // B*N*K    (stats count for diff channels)

// Scratch (static device globals — allocation-free per harness rules)
__device__ float g_localT[BB*NPTS*OO];   // (B,N,O) 16 MB
__device__ float g_edgeT [BB*NPTS*OO];   // (B,N,O) 16 MB
__device__ float g_acc[512];             // [0:128) sum_l [128:256) sq_l [256:384) sum_d [384:512) sq_d

// ---------------------------------------------------------------------------
// K1: dual GEMM.  localT[b][n][o] = sum_c W1[o][c]*f[b][c][n]; edgeT with W2.
// Block: one batch, 64-wide n tile, all 256 outputs. K staged in 32-chunks.
// Thread tile: 4 n  x 16 o  (64 accumulators).
// ---------------------------------------------------------------------------
__global__ void __launch_bounds__(256) k_gemm(const float* __restrict__ feat,
                                              const float* __restrict__ W1,
                                              const float* __restrict__ W2) {
    __shared__ float Wt[32 * 256];   // Wt[kk][o]  (o in [0,256): W1 | W2)
    __shared__ float ft[32 * 64];    // ft[kk][nn]

    const int tid = threadIdx.x;
    if (blockIdx.x == 0) {           // re-zero stat accumulators every replay
        for (int t = tid; t < 512; t += 256) g_acc[t] = 0.f;
    }
    const int b  = blockIdx.x >> 7;
    const int n0 = (blockIdx.x & 127) << 6;

    const float* fb = feat + b * (CC * NPTS) + n0;

    const int tn = (tid & 15) << 2;   // n offset within tile (4 consecutive)
    const int to = (tid >> 4) << 4;   // o offset (16 consecutive), groups don't straddle 128

    float acc[64];
#pragma unroll
    for (int i = 0; i < 64; i++) acc[i] = 0.f;

    for (int kc = 0; kc < 128; kc += 32) {
        __syncthreads();   // protect previous chunk's smem
        // stage W chunk (transposed): 2 weights x 128 o x 32 k / 4 = 2048 float4
#pragma unroll
        for (int it = 0; it < 8; ++it) {
            int f4i  = tid + it * 256;       // 0..2047
            int wsel = f4i >> 10;            // 0: W1, 1: W2
            int rem  = f4i & 1023;
            int o    = rem & 127;            // consecutive across a warp -> conflict-free STS
            int c0   = (rem >> 7) << 2;      // k-within-chunk, multiple of 4
            const float4 wv = *(const float4*)((wsel ? W2 : W1) + o * 128 + kc + c0);
            int ocol = o + (wsel << 7);
            Wt[(c0 + 0) * 256 + ocol] = wv.x;
            Wt[(c0 + 1) * 256 + ocol] = wv.y;
            Wt[(c0 + 2) * 256 + ocol] = wv.z;
            Wt[(c0 + 3) * 256 + ocol] = wv.w;
        }
        // stage feature chunk: 32 k-rows x 64 n
#pragma unroll
        for (int it = 0; it < 8; ++it) {
            int idx = tid + it * 256;        // 0..2047
            int cc  = idx >> 6;
            int nn  = idx & 63;
            ft[idx] = fb[(kc + cc) * NPTS + nn];
        }
        __syncthreads();

#pragma unroll 8
        for (int kk = 0; kk < 32; ++kk) {
            const float4 fv = *(const float4*)&ft[kk * 64 + tn];
            const float fa[4] = {fv.x, fv.y, fv.z, fv.w};
#pragma unroll
            for (int j = 0; j < 4; ++j) {
                const float4 wv = *(const float4*)&Wt[kk * 256 + to + 4 * j];
                const float wa[4] = {wv.x, wv.y, wv.z, wv.w};
#pragma unroll
                for (int i = 0; i < 4; ++i) {
#pragma unroll
                    for (int m = 0; m < 4; ++m)
                        acc[i * 16 + j * 4 + m] += fa[i] * wa[m];
                }
            }
        }
    }

    // store: this thread's 16 o's are entirely in local (to<128) or edge
    float* dst = (to < 128) ? g_localT : g_edgeT;
    const int col0 = to & 127;
#pragma unroll
    for (int i = 0; i < 4; ++i) {
        const int n = n0 + tn + i;
        float* row = dst + ((b * NPTS + n) << 7) + col0;
#pragma unroll
        for (int j = 0; j < 4; ++j) {
            float4 v = make_float4(acc[i * 16 + j * 4 + 0], acc[i * 16 + j * 4 + 1],
                                   acc[i * 16 + j * 4 + 2], acc[i * 16 + j * 4 + 3]);
            *(float4*)(row + 4 * j) = v;
        }
    }
}

// ---------------------------------------------------------------------------
// K2: BN statistics. Warp per point (64 points/block, grid 512).
// Lane owns 4 channels (float4 slice). Registers -> shared atomics -> global.
// ---------------------------------------------------------------------------
__global__ void __launch_bounds__(256) k_stats(const int* __restrict__ knn) {
    const int tid = threadIdx.x, lane = tid & 31, warp = tid >> 5;

    float sl[4]  = {0.f, 0.f, 0.f, 0.f};
    float sql[4] = {0.f, 0.f, 0.f, 0.f};
    float sd[4]  = {0.f, 0.f, 0.f, 0.f};
    float sqd[4] = {0.f, 0.f, 0.f, 0.f};

    const int pbase = blockIdx.x * 64 + warp * 8;
    const int c0 = lane << 2;

    for (int iter = 0; iter < 8; ++iter) {
        const int p = pbase + iter;               // p = b*8192 + n
        const int b = p >> 13;
        int myidx = 0;
        if (lane < 16) myidx = knn[p * 16 + lane];

        const float4 lv = *(const float4*)&g_localT[(p << 7) + c0];
        sl[0] += lv.x; sql[0] += lv.x * lv.x;
        sl[1] += lv.y; sql[1] += lv.y * lv.y;
        sl[2] += lv.z; sql[2] += lv.z * lv.z;
        sl[3] += lv.w; sql[3] += lv.w * lv.w;

        const float* eb = g_edgeT + ((size_t)b << 20);
#pragma unroll
        for (int k = 0; k < 16; ++k) {
            const int ik = __shfl_sync(0xffffffffu, myidx, k);
            const float4 ev = *(const float4*)&eb[(ik << 7) + c0];
            float d0 = ev.x - lv.x; sd[0] += d0; sqd[0] += d0 * d0;
            float d1 = ev.y - lv.y; sd[1] += d1; sqd[1] += d1 * d1;
            float d2 = ev.z - lv.z; sd[2] += d2; sqd[2] += d2 * d2;
            float d3 = ev.w - lv.w; sd[3] += d3; sqd[3] += d3 * d3;
        }
    }

    __shared__ float sacc[512];
    for (int t = tid; t < 512; t += 256) sacc[t] = 0.f;
    __syncthreads();
#pragma unroll
    for (int j = 0; j < 4; ++j) {
        atomicAdd(&sacc[c0 + j],        sl[j]);
        atomicAdd(&sacc[128 + c0 + j],  sql[j]);
        atomicAdd(&sacc[256 + c0 + j],  sd[j]);
        atomicAdd(&sacc[384 + c0 + j],  sqd[j]);
    }
    __syncthreads();
    for (int t = tid; t < 512; t += 256) atomicAdd(&g_acc[t], sacc[t]);
}

// ---------------------------------------------------------------------------
// K3: output. Block = (batch b, 32-wide n tile). Warp per point; each block
// derives BN scale/shift from g_acc. Results transposed through padded smem
// so the (B,256,N) store is coalesced.
// ---------------------------------------------------------------------------
__global__ void __launch_bounds__(256) k_out(const int* __restrict__ knn,
                                             const float* __restrict__ gamma,
                                             const float* __restrict__ beta,
                                             float* __restrict__ out) {
    __shared__ float s_a[256], s_sh[256];
    __shared__ float s_o1[128 * 33];
    __shared__ float s_o2[128 * 33];

    const int tid = threadIdx.x;
    {   // derive BN affine params (256 threads, one channel each)
        const int ch = tid;
        float s, sq, inv_cnt;
        if (ch < 128) { s = g_acc[ch];       sq = g_acc[128 + ch]; inv_cnt = 1.f / CNT1; }
        else          { s = g_acc[128 + ch]; sq = g_acc[256 + ch]; inv_cnt = 1.f / CNT2; }
        const float mean = s * inv_cnt;
        const float var  = fmaxf(sq * inv_cnt - mean * mean, 0.f);
        const float a    = gamma[ch] * rsqrtf(var + 1e-5f);
        s_a[ch]  = a;
        s_sh[ch] = beta[ch] - a * mean;
    }
    __syncthreads();

    const int b  = blockIdx.x >> 8;
    const int n0 = (blockIdx.x & 255) << 5;
    const int lane = tid & 31, warp = tid >> 5;
    const int c0 = lane << 2;

    float a1[4], sh1[4], a2[4], sh2[4];
#pragma unroll
    for (int j = 0; j < 4; ++j) {
        a1[j]  = s_a[c0 + j];        sh1[j] = s_sh[c0 + j];
        a2[j]  = s_a[128 + c0 + j];  sh2[j] = s_sh[128 + c0 + j];
    }

    const float* eb = g_edgeT + ((size_t)b << 20);
    for (int iter = 0; iter < 4; ++iter) {
        const int i = warp * 4 + iter;           // 0..31
        const int p = (b << 13) + n0 + i;
        int myidx = 0;
        if (lane < 16) myidx = knn[p * 16 + lane];

        const float4 lv = *(const float4*)&g_localT[(p << 7) + c0];
        const float l[4] = {lv.x, lv.y, lv.z, lv.w};
        float accf[4] = {0.f, 0.f, 0.f, 0.f};
#pragma unroll
        for (int k = 0; k < 16; ++k) {
            const int ik = __shfl_sync(0xffffffffu, myidx, k);
            const float4 ev = *(const float4*)&eb[(ik << 7) + c0];
            const float e[4] = {ev.x, ev.y, ev.z, ev.w};
#pragma unroll
            for (int j = 0; j < 4; ++j)
                accf[j] += fmaxf(a2[j] * (e[j] - l[j]) + sh2[j], 0.f);
        }
#pragma unroll
        for (int j = 0; j < 4; ++j) {
            s_o1[(c0 + j) * 33 + i] = fmaxf(a1[j] * l[j] + sh1[j], 0.f);
            s_o2[(c0 + j) * 33 + i] = accf[j] * (1.f / 16.f);
        }
    }
    __syncthreads();

    float* ob = out + ((size_t)b << 21) + n0;    // b*256*8192
#pragma unroll
    for (int r = 0; r < 16; ++r) {
        const int t  = tid + (r << 8);
        const int c  = t >> 5;
        const int i2 = t & 31;
        ob[(size_t)c * NPTS + i2]         = s_o1[c * 33 + i2];
        ob[(size_t)(c + 128) * NPTS + i2] = s_o2[c * 33 + i2];
    }
}

// ---------------------------------------------------------------------------
extern "C" void kernel_launch(void* const* d_in, const int* in_sizes, int n_in,
                              void* d_out, int out_size) {
    const float* feat  = (const float*)d_in[0];
    const int*   knn   = (const int*)  d_in[1];
    const float* W1    = (const float*)d_in[2];
    const float* W2    = (const float*)d_in[3];
    const float* gamma = (const float*)d_in[4];
    const float* beta  = (const float*)d_in[5];
    float* out = (float*)d_out;

    k_gemm <<<512, 256>>>(feat, W1, W2);
    k_stats<<<512, 256>>>(knn);
    k_out  <<<1024, 256>>>(knn, gamma, beta, out);
}

// round 8
// speedup vs baseline: 2.3134x; 2.3134x over previous
#include <cuda_runtime.h>

// Shapes (fixed by the problem)
#define BB   4
#define CC   128
#define NPTS 8192
#define KNN  16
#define OO   128
#define CNT1 32768.0f                // B*N      (stats count for central channels)
#define CNT2 524288.0f               // B*N*K    (stats count for diff channels)

// Scratch (static device globals — allocation-free per harness rules)
__device__ float g_localT[BB*NPTS*OO];   // (B,N,O) 16 MB
__device__ float g_edgeT [BB*NPTS*OO];   // (B,N,O) 16 MB
__device__ float g_acc[512];             // [0:128) sum_l [128:256) sq_l [256:384) sum_d [384:512) sq_d

// ---------------------------------------------------------------------------
// helpers: tf32 convert + mma.sync m16n8k8
// ---------------------------------------------------------------------------
__device__ __forceinline__ unsigned f2tf32(float x) {
    unsigned y;
    asm("cvt.rna.tf32.f32 %0, %1;" : "=r"(y) : "f"(x));
    return y;
}

__device__ __forceinline__ void mma_tf32(float c[4], const unsigned a[4], const unsigned b[2]) {
    asm("mma.sync.aligned.m16n8k8.row.col.f32.tf32.tf32.f32 "
        "{%0,%1,%2,%3}, {%4,%5,%6,%7}, {%8,%9}, {%0,%1,%2,%3};"
        : "+f"(c[0]), "+f"(c[1]), "+f"(c[2]), "+f"(c[3])
        : "r"(a[0]), "r"(a[1]), "r"(a[2]), "r"(a[3]),
          "r"(b[0]), "r"(b[1]));
}

// ---------------------------------------------------------------------------
// K1: dual GEMM via tf32 tensor cores.
//   C[m][n] = sum_c W[m][c] * feat[b][c][n0+n]   (m = output channel)
// Block tile: 128 channels (mb picks W1 or W2) x 128 points, K=128 in 32-chunks.
// 8 warps: warp grid 2(m) x 4(n), warp tile 64x32, mma m16n8k8.
// Stores transposed (B,N,O) to g_localT / g_edgeT (o contiguous).
// ---------------------------------------------------------------------------
__global__ void __launch_bounds__(256, 2) k_gemm(const float* __restrict__ feat,
                                                 const float* __restrict__ W1,
                                                 const float* __restrict__ W2) {
    __shared__ float smem_s[2 * 32 * 132];     // As[32][132] | Bs[32][132]  (33.8 KB)
    float* As = smem_s;                        // As[k][m] = tf32(W[m][kc+k])
    float* Bs = smem_s + 32 * 132;             // Bs[k][n] = tf32(feat[b][kc+k][n0+n])

    const int tid = threadIdx.x;
    if (blockIdx.x == 0) {                     // re-zero stat accumulators every replay
        for (int t = tid; t < 512; t += 256) g_acc[t] = 0.f;
    }
    const int mb = blockIdx.x >> 8;            // 0: W1 -> localT, 1: W2 -> edgeT
    const int b  = (blockIdx.x >> 6) & 3;
    const int n0 = (blockIdx.x & 63) << 7;

    const float* Wsel = mb ? W2 : W1;
    const float* fb   = feat + b * (CC * NPTS) + n0;

    const int wid  = tid >> 5, lane = tid & 31;
    const int wm   = (wid >> 2) << 6;          // warp m base: 0 or 64
    const int wn   = (wid & 3) << 5;           // warp n base: 0..96
    const int g    = lane >> 2;                // group id (0..7)
    const int tig  = lane & 3;                 // thread in group (0..3)

    float acc[4][4][4];
#pragma unroll
    for (int mt = 0; mt < 4; ++mt)
#pragma unroll
        for (int nt = 0; nt < 4; ++nt)
#pragma unroll
            for (int q = 0; q < 4; ++q) acc[mt][nt][q] = 0.f;

    for (int kc = 0; kc < 128; kc += 32) {
        __syncthreads();
        // ---- stage A: W rows, transposed into As[k][m] (tf32) ----
#pragma unroll
        for (int t = 0; t < 4; ++t) {
            const int i  = tid + (t << 8);     // 0..1023 float4s
            const int m  = i >> 3;             // 0..127
            const int jj = i & 7;              // k/4 within chunk
            const float4 v = *(const float4*)(Wsel + m * 128 + kc + (jj << 2));
            As[((jj << 2) + 0) * 132 + m] = __uint_as_float(f2tf32(v.x));
            As[((jj << 2) + 1) * 132 + m] = __uint_as_float(f2tf32(v.y));
            As[((jj << 2) + 2) * 132 + m] = __uint_as_float(f2tf32(v.z));
            As[((jj << 2) + 3) * 132 + m] = __uint_as_float(f2tf32(v.w));
        }
        // ---- stage B: feat rows (coalesced along n) into Bs[k][n] (tf32) ----
#pragma unroll
        for (int t = 0; t < 4; ++t) {
            const int i  = tid + (t << 8);     // 0..1023 float4s
            const int kk = i >> 5;             // 0..31
            const int nf = i & 31;
            const float4 v = *(const float4*)(fb + (kc + kk) * NPTS + (nf << 2));
            float4 o;
            o.x = __uint_as_float(f2tf32(v.x));
            o.y = __uint_as_float(f2tf32(v.y));
            o.z = __uint_as_float(f2tf32(v.z));
            o.w = __uint_as_float(f2tf32(v.w));
            *(float4*)&Bs[kk * 132 + (nf << 2)] = o;
        }
        __syncthreads();

        // ---- 4 k-steps of 8 ----
#pragma unroll
        for (int ks = 0; ks < 4; ++ks) {
            const int k0 = ks << 3;
            const float* A0 = As + (k0 + tig) * 132;
            const float* A1 = As + (k0 + tig + 4) * 132;
            const float* B0 = Bs + (k0 + tig) * 132;
            const float* B1 = Bs + (k0 + tig + 4) * 132;

            unsigned afr[4][4], bfr[4][2];
#pragma unroll
            for (int mt = 0; mt < 4; ++mt) {
                const int r = wm + (mt << 4) + g;
                afr[mt][0] = __float_as_uint(A0[r]);
                afr[mt][1] = __float_as_uint(A0[r + 8]);
                afr[mt][2] = __float_as_uint(A1[r]);
                afr[mt][3] = __float_as_uint(A1[r + 8]);
            }
#pragma unroll
            for (int nt = 0; nt < 4; ++nt) {
                const int c = wn + (nt << 3) + g;
                bfr[nt][0] = __float_as_uint(B0[c]);
                bfr[nt][1] = __float_as_uint(B1[c]);
            }
#pragma unroll
            for (int mt = 0; mt < 4; ++mt)
#pragma unroll
                for (int nt = 0; nt < 4; ++nt)
                    mma_tf32(acc[mt][nt], afr[mt], bfr[nt]);
        }
    }

    // ---- epilogue: per-warp transpose via smem (reuse staging region) ----
    __syncthreads();                            // all warps done reading As/Bs
    float* wb = smem_s + wid * 544;             // per-warp [8][68]
    float* dst = mb ? g_edgeT : g_localT;

#pragma unroll
    for (int nt = 0; nt < 4; ++nt) {
        __syncwarp();
#pragma unroll
        for (int mt = 0; mt < 4; ++mt) {
            float* wr0 = wb + (2 * tig) * 68 + (mt << 4) + g;
            float* wr1 = wb + (2 * tig + 1) * 68 + (mt << 4) + g;
            wr0[0] = acc[mt][nt][0];            // (row g,   col 2tig)
            wr1[0] = acc[mt][nt][1];            // (row g,   col 2tig+1)
            wr0[8] = acc[mt][nt][2];            // (row g+8, col 2tig)
            wr1[8] = acc[mt][nt][3];            // (row g+8, col 2tig+1)
        }
        __syncwarp();
#pragma unroll
        for (int r = 0; r < 4; ++r) {
            const int j  = lane + (r << 5);     // 0..127
            const int nl = j >> 4;              // 0..7 (local n)
            const int mq = (j & 15) << 2;       // 0..60 (m offset)
            const float4 v = *(const float4*)&wb[nl * 68 + mq];
            const int n = n0 + wn + (nt << 3) + nl;
            *(float4*)&dst[((size_t)(b * NPTS + n) << 7) + wm + mq] = v;
        }
    }
}

// ---------------------------------------------------------------------------
// K2: BN statistics. Warp per point (64 points/block, grid 512).
// Lane owns 4 channels (float4 slice). Registers -> shared atomics -> global.
// ---------------------------------------------------------------------------
__global__ void __launch_bounds__(256) k_stats(const int* __restrict__ knn) {
    const int tid = threadIdx.x, lane = tid & 31, warp = tid >> 5;

    float sl[4]  = {0.f, 0.f, 0.f, 0.f};
    float sql[4] = {0.f, 0.f, 0.f, 0.f};
    float sd[4]  = {0.f, 0.f, 0.f, 0.f};
    float sqd[4] = {0.f, 0.f, 0.f, 0.f};

    const int pbase = blockIdx.x * 64 + warp * 8;
    const int c0 = lane << 2;

    for (int iter = 0; iter < 8; ++iter) {
        const int p = pbase + iter;               // p = b*8192 + n
        const int b = p >> 13;
        int myidx = 0;
        if (lane < 16) myidx = knn[p * 16 + lane];

        const float4 lv = *(const float4*)&g_localT[(p << 7) + c0];
        sl[0] += lv.x; sql[0] += lv.x * lv.x;
        sl[1] += lv.y; sql[1] += lv.y * lv.y;
        sl[2] += lv.z; sql[2] += lv.z * lv.z;
        sl[3] += lv.w; sql[3] += lv.w * lv.w;

        const float* eb = g_edgeT + ((size_t)b << 20);
#pragma unroll
        for (int k = 0; k < 16; ++k) {
            const int ik = __shfl_sync(0xffffffffu, myidx, k);
            const float4 ev = *(const float4*)&eb[(ik << 7) + c0];
            float d0 = ev.x - lv.x; sd[0] += d0; sqd[0] += d0 * d0;
            float d1 = ev.y - lv.y; sd[1] += d1; sqd[1] += d1 * d1;
            float d2 = ev.z - lv.z; sd[2] += d2; sqd[2] += d2 * d2;
            float d3 = ev.w - lv.w; sd[3] += d3; sqd[3] += d3 * d3;
        }
    }

    __shared__ float sacc[512];
    for (int t = tid; t < 512; t += 256) sacc[t] = 0.f;
    __syncthreads();
#pragma unroll
    for (int j = 0; j < 4; ++j) {
        atomicAdd(&sacc[c0 + j],        sl[j]);
        atomicAdd(&sacc[128 + c0 + j],  sql[j]);
        atomicAdd(&sacc[256 + c0 + j],  sd[j]);
        atomicAdd(&sacc[384 + c0 + j],  sqd[j]);
    }
    __syncthreads();
    for (int t = tid; t < 512; t += 256) atomicAdd(&g_acc[t], sacc[t]);
}

// ---------------------------------------------------------------------------
// K3: output. Block = (batch b, 32-wide n tile). Warp per point; each block
// derives BN scale/shift from g_acc. Results transposed through padded smem
// so the (B,256,N) store is coalesced.
// ---------------------------------------------------------------------------
__global__ void __launch_bounds__(256) k_out(const int* __restrict__ knn,
                                             const float* __restrict__ gamma,
                                             const float* __restrict__ beta,
                                             float* __restrict__ out) {
    __shared__ float s_a[256], s_sh[256];
    __shared__ float s_o1[128 * 33];
    __shared__ float s_o2[128 * 33];

    const int tid = threadIdx.x;
    {   // derive BN affine params (256 threads, one channel each)
        const int ch = tid;
        float s, sq, inv_cnt;
        if (ch < 128) { s = g_acc[ch];       sq = g_acc[128 + ch]; inv_cnt = 1.f / CNT1; }
        else          { s = g_acc[128 + ch]; sq = g_acc[256 + ch]; inv_cnt = 1.f / CNT2; }
        const float mean = s * inv_cnt;
        const float var  = fmaxf(sq * inv_cnt - mean * mean, 0.f);
        const float a    = gamma[ch] * rsqrtf(var + 1e-5f);
        s_a[ch]  = a;
        s_sh[ch] = beta[ch] - a * mean;
    }
    __syncthreads();

    const int b  = blockIdx.x >> 8;
    const int n0 = (blockIdx.x & 255) << 5;
    const int lane = tid & 31, warp = tid >> 5;
    const int c0 = lane << 2;

    float a1[4], sh1[4], a2[4], sh2[4];
#pragma unroll
    for (int j = 0; j < 4; ++j) {
        a1[j]  = s_a[c0 + j];        sh1[j] = s_sh[c0 + j];
        a2[j]  = s_a[128 + c0 + j];  sh2[j] = s_sh[128 + c0 + j];
    }

    const float* eb = g_edgeT + ((size_t)b << 20);
    for (int iter = 0; iter < 4; ++iter) {
        const int i = warp * 4 + iter;           // 0..31
        const int p = (b << 13) + n0 + i;
        int myidx = 0;
        if (lane < 16) myidx = knn[p * 16 + lane];

        const float4 lv = *(const float4*)&g_localT[(p << 7) + c0];
        const float l[4] = {lv.x, lv.y, lv.z, lv.w};
        float accf[4] = {0.f, 0.f, 0.f, 0.f};
#pragma unroll
        for (int k = 0; k < 16; ++k) {
            const int ik = __shfl_sync(0xffffffffu, myidx, k);
            const float4 ev = *(const float4*)&eb[(ik << 7) + c0];
            const float e[4] = {ev.x, ev.y, ev.z, ev.w};
#pragma unroll
            for (int j = 0; j < 4; ++j)
                accf[j] += fmaxf(a2[j] * (e[j] - l[j]) + sh2[j], 0.f);
        }
#pragma unroll
        for (int j = 0; j < 4; ++j) {
            s_o1[(c0 + j) * 33 + i] = fmaxf(a1[j] * l[j] + sh1[j], 0.f);
            s_o2[(c0 + j) * 33 + i] = accf[j] * (1.f / 16.f);
        }
    }
    __syncthreads();

    float* ob = out + ((size_t)b << 21) + n0;    // b*256*8192
#pragma unroll
    for (int r = 0; r < 16; ++r) {
        const int t  = tid + (r << 8);
        const int c  = t >> 5;
        const int i2 = t & 31;
        ob[(size_t)c * NPTS + i2]         = s_o1[c * 33 + i2];
        ob[(size_t)(c + 128) * NPTS + i2] = s_o2[c * 33 + i2];
    }
}

// ---------------------------------------------------------------------------
extern "C" void kernel_launch(void* const* d_in, const int* in_sizes, int n_in,
                              void* d_out, int out_size) {
    const float* feat  = (const float*)d_in[0];
    const int*   knn   = (const int*)  d_in[1];
    const float* W1    = (const float*)d_in[2];
    const float* W2    = (const float*)d_in[3];
    const float* gamma = (const float*)d_in[4];
    const float* beta  = (const float*)d_in[5];
    float* out = (float*)d_out;

    k_gemm <<<512, 256>>>(feat, W1, W2);
    k_stats<<<512, 256>>>(knn);
    k_out  <<<1024, 256>>>(knn, gamma, beta, out);
}